// round 12
// baseline (speedup 1.0000x reference)
#include <cuda_runtime.h>
#include <cuda_fp16.h>
#include <math.h>
#include <cstdint>

#define BSROWS 8192
#define SEQ    2048
#define DIM    1024
#define NH     16
#define DFF    4096

// ---------------------------------------------------------------------------
// Scratch (device globals)
// ---------------------------------------------------------------------------
__device__ __half g_lnh  [8388608];    // LN output (reused LN1/LN2)
__device__ __half g_vh   [8388608];    // v = LN1@W_in + b_in
__device__ __half g_a2h  [1048576];    // A rearranged [h][j*32+i][p]
__device__ __half g_Mh   [134217728];  // M[h][bs][j*32+i]   (268MB)
__device__ __half g_hsh  [4194304];    // recurrence out [bs][H*DH]
__device__ float  g_x2   [8388608];    // x + hs@W_out + b_out (fp32 residual)
__device__ __half g_ffnh [33554432];   // GELU(LN2@W1+b1)
__device__ __half g_winh [1048576];    // W_in^T  [1024][1024]
__device__ __half g_wouth[524288];     // W_out^T [1024][512]
__device__ __half g_w1h  [4194304];    // W1^T    [4096][1024]
__device__ __half g_w2h  [4194304];    // W2^T    [1024][4096]

// ---------------------------------------------------------------------------
// Helpers
// ---------------------------------------------------------------------------
__device__ __forceinline__ uint32_t smem_u32(const void* p) {
    return (uint32_t)__cvta_generic_to_shared(p);
}
__device__ __forceinline__ float gelu_exact(float x) {
    return 0.5f * x * (1.0f + erff(x * 0.70710678118654752f));
}
__device__ __forceinline__ void cp16(uint32_t dst, const void* src) {
    asm volatile("cp.async.cg.shared.global [%0], [%1], 16;" :: "r"(dst), "l"(src));
}
__device__ __forceinline__ float tanh_fast(float x) {
    float r;
    asm("tanh.approx.f32 %0, %1;" : "=f"(r) : "f"(x));
    return r;
}
__device__ __forceinline__ void mma_f16(float* d, const uint32_t* a, const uint32_t* b) {
    asm volatile(
        "mma.sync.aligned.m16n8k16.row.col.f32.f16.f16.f32 "
        "{%0,%1,%2,%3}, {%4,%5,%6,%7}, {%8,%9}, {%0,%1,%2,%3};"
        : "+f"(d[0]), "+f"(d[1]), "+f"(d[2]), "+f"(d[3])
        : "r"(a[0]), "r"(a[1]), "r"(a[2]), "r"(a[3]),
          "r"(b[0]), "r"(b[1]));
}
__device__ __forceinline__ void ldsm4(uint32_t& r0, uint32_t& r1, uint32_t& r2,
                                      uint32_t& r3, uint32_t addr) {
    asm volatile("ldmatrix.sync.aligned.m8n8.x4.shared.b16 {%0,%1,%2,%3}, [%4];"
                 : "=r"(r0), "=r"(r1), "=r"(r2), "=r"(r3) : "r"(addr));
}

// ---------------------------------------------------------------------------
// prep: A[h][i][p][j] -> a2h[h][j*32+i][p]  (fp16)
// ---------------------------------------------------------------------------
__global__ void prep_A_kernel(const float* __restrict__ A, __half* __restrict__ A2) {
    int idx = blockIdx.x * 256 + threadIdx.x;
    int j = idx & 31;
    int p = (idx >> 5) & 63;
    int i = (idx >> 11) & 31;
    int h = idx >> 16;
    A2[(size_t)h * 65536 + (size_t)(j * 32 + i) * 64 + p] = __float2half(A[idx]);
}

// ---------------------------------------------------------------------------
// Merged weight transposes (fp32 [R][C] -> fp16 [C][R]).
// ---------------------------------------------------------------------------
__device__ __forceinline__ void ttile(const float* __restrict__ in,
                                      __half* __restrict__ out,
                                      int R, int C, int bx, int by) {
    __shared__ float t[32][33];
    int tx = threadIdx.x, ty = threadIdx.y;
    int x0 = bx * 32, y0 = by * 32;
#pragma unroll
    for (int j = 0; j < 32; j += 8)
        t[ty + j][tx] = in[(size_t)(y0 + ty + j) * C + x0 + tx];
    __syncthreads();
#pragma unroll
    for (int j = 0; j < 32; j += 8)
        out[(size_t)(x0 + ty + j) * R + y0 + tx] = __float2half(t[tx][ty + j]);
}

__global__ void tconv_all_kernel(const float* __restrict__ W1, __half* __restrict__ w1h,
                                 const float* __restrict__ W2, __half* __restrict__ w2h,
                                 const float* __restrict__ Wi, __half* __restrict__ wih,
                                 const float* __restrict__ Wo, __half* __restrict__ woh)
{
    int t = blockIdx.x;
    if (t < 4096)        ttile(W1, w1h, 1024, 4096, t & 127, t >> 7);
    else if (t < 8192)   { t -= 4096; ttile(W2, w2h, 4096, 1024, t & 31, t >> 5); }
    else if (t < 9216)   { t -= 8192; ttile(Wi, wih, 1024, 1024, t & 31, t >> 5); }
    else                 { t -= 9216; ttile(Wo, woh, 512, 1024, t & 31, t >> 5); }
}

// ---------------------------------------------------------------------------
// LayerNorm (fp32 in, fp16 out).
// ---------------------------------------------------------------------------
__global__ void ln_h_kernel(const float* __restrict__ x, const float* __restrict__ g,
                            const float* __restrict__ b, __half* __restrict__ y) {
    int row = blockIdx.x;
    int tid = threadIdx.x;
    const float* xr = x + (size_t)row * DIM;
    float v[4];
    float s = 0.f, sq = 0.f;
#pragma unroll
    for (int i = 0; i < 4; i++) {
        v[i] = xr[tid + i * 256];
        s  += v[i];
        sq += v[i] * v[i];
    }
#pragma unroll
    for (int o = 16; o > 0; o >>= 1) {
        s  += __shfl_xor_sync(0xffffffffu, s,  o);
        sq += __shfl_xor_sync(0xffffffffu, sq, o);
    }
    __shared__ float ss[8], sqq[8];
    int w = tid >> 5, l = tid & 31;
    if (l == 0) { ss[w] = s; sqq[w] = sq; }
    __syncthreads();
    if (w == 0) {
        s  = (l < 8) ? ss[l]  : 0.f;
        sq = (l < 8) ? sqq[l] : 0.f;
#pragma unroll
        for (int o = 4; o > 0; o >>= 1) {
            s  += __shfl_xor_sync(0xffffffffu, s,  o);
            sq += __shfl_xor_sync(0xffffffffu, sq, o);
        }
        if (l == 0) { ss[0] = s; sqq[0] = sq; }
    }
    __syncthreads();
    s = ss[0]; sq = sqq[0];
    float mean = s * (1.0f / DIM);
    float var  = sq * (1.0f / DIM) - mean * mean;
    float rstd = rsqrtf(var + 1e-5f);
    __half* yr = y + (size_t)row * DIM;
#pragma unroll
    for (int i = 0; i < 4; i++) {
        int c = tid + i * 256;
        yr[c] = __float2half((v[i] - mean) * rstd * g[c] + b[c]);
    }
}

// ---------------------------------------------------------------------------
// fp16 warp-MMA GEMM, BK=64, 2-stage cp.async, ldmatrix fragments.
// C[M,N] = A[M,K] @ BT[N,K]^T  (fp32 accumulate)
// CTA 128x128, 8 warps (64x32), mma.m16n8k16.
// SMEM: A/B each [2][128][72] halves.  ONE STAGE = 128*72*2 = 18432 BYTES —
// stage stride is 18432 bytes (NOT the 2-stage total; that bug crashed R11).
// Stride 144B rows -> conflict-free ldmatrix (row g at word 36g mod 32 = 4g).
// Requires K%64==0. EPI: bit0=bias, bit1=residual(float), bit2=gelu.
// ---------------------------------------------------------------------------
#define HSMEM_BYTES 73728
#define STAGE_BYTES 18432

template <int EPI, typename OT>
__global__ void __launch_bounds__(256, 2) hgemm(
    const __half* __restrict__ A, const __half* __restrict__ BT, OT* __restrict__ C,
    const float* __restrict__ bias, const float* __restrict__ res,
    int K, int lda, int ldb, int ldc,
    size_t batchA, size_t batchB, size_t batchC)
{
    extern __shared__ __half hsm[];
    __half* As = hsm;            // [2][128][72]
    __half* Bs = hsm + 18432;    // halves offset = 2 stages of A = 36864 bytes

    A  += (size_t)blockIdx.z * batchA;
    BT += (size_t)blockIdx.z * batchB;
    C  += (size_t)blockIdx.z * batchC;

    const int tid = threadIdx.x;
    const int m0 = blockIdx.y * 128, n0 = blockIdx.x * 128;
    const int wid = tid >> 5, lane = tid & 31;
    const int wm = (wid >> 2) * 64;
    const int wn = (wid & 3) * 32;
    const int gq = lane >> 2, tg = lane & 3;

    const uint32_t sA = smem_u32(As);
    const uint32_t sB = smem_u32(Bs);

    const int row = tid >> 1, quad = tid & 1;   // gmem->smem: 2 thr per 128B row

    auto loadA = [&](int st, int k0) {
        const __half* src = A + (size_t)(m0 + row) * lda + k0 + quad * 32;
        uint32_t dst = sA + (uint32_t)st * STAGE_BYTES + (uint32_t)row * 144 + (uint32_t)quad * 64;
        cp16(dst, src);           cp16(dst + 16, src + 8);
        cp16(dst + 32, src + 16); cp16(dst + 48, src + 24);
    };
    auto loadB = [&](int st, int k0) {
        const __half* src = BT + (size_t)(n0 + row) * ldb + k0 + quad * 32;
        uint32_t dst = sB + (uint32_t)st * STAGE_BYTES + (uint32_t)row * 144 + (uint32_t)quad * 64;
        cp16(dst, src);           cp16(dst + 16, src + 8);
        cp16(dst + 32, src + 16); cp16(dst + 48, src + 24);
    };

    // ldmatrix per-lane byte offsets (within a stage)
    const int arow_l = (lane & 7) | (((lane >> 3) & 1) << 3);  // 0..15
    const int aseg   = lane >> 4;                              // k half (8 halves)
    const uint32_t aoffB = (uint32_t)(wm + arow_l) * 144 + (uint32_t)aseg * 16;
    const int brow_l = (lane & 7) + ((lane >> 4) << 3);
    const int bseg   = (lane >> 3) & 1;
    const uint32_t boffB = (uint32_t)(wn + brow_l) * 144 + (uint32_t)bseg * 16;

    float acc[4][4][4];
#pragma unroll
    for (int mi = 0; mi < 4; mi++)
#pragma unroll
        for (int ni = 0; ni < 4; ni++)
#pragma unroll
            for (int q = 0; q < 4; q++) acc[mi][ni][q] = 0.f;

    const int KT = K >> 6;
    loadA(0, 0); loadB(0, 0);
    asm volatile("cp.async.commit_group;");

    for (int kt = 0; kt < KT; ++kt) {
        asm volatile("cp.async.wait_group 0;");
        __syncthreads();
        if (kt + 1 < KT) {
            loadA((kt + 1) & 1, (kt + 1) * 64);
            loadB((kt + 1) & 1, (kt + 1) * 64);
            asm volatile("cp.async.commit_group;");
        }

        const uint32_t aB = sA + (uint32_t)(kt & 1) * STAGE_BYTES + aoffB;
        const uint32_t bB = sB + (uint32_t)(kt & 1) * STAGE_BYTES + boffB;
#pragma unroll
        for (int kk = 0; kk < 64; kk += 16) {
            uint32_t a[4][4], b[4][2];
#pragma unroll
            for (int mi = 0; mi < 4; mi++)
                ldsm4(a[mi][0], a[mi][1], a[mi][2], a[mi][3],
                      aB + (uint32_t)mi * (16 * 144) + (uint32_t)kk * 2);
#pragma unroll
            for (int p = 0; p < 2; p++)
                ldsm4(b[2 * p][0], b[2 * p][1], b[2 * p + 1][0], b[2 * p + 1][1],
                      bB + (uint32_t)p * (16 * 144) + (uint32_t)kk * 2);
#pragma unroll
            for (int mi = 0; mi < 4; mi++)
#pragma unroll
                for (int ni = 0; ni < 4; ni++)
                    mma_f16(acc[mi][ni], a[mi], b[ni]);
        }
    }

    // epilogue
#pragma unroll
    for (int mi = 0; mi < 4; mi++) {
        const int r0 = m0 + wm + mi * 16 + gq;
#pragma unroll
        for (int ni = 0; ni < 4; ni++) {
            const int c = n0 + wn + ni * 8 + 2 * tg;
            float2 v01 = make_float2(acc[mi][ni][0], acc[mi][ni][1]);
            float2 v23 = make_float2(acc[mi][ni][2], acc[mi][ni][3]);
            if (EPI & 1) {
                float2 bv = *(const float2*)(bias + c);
                v01.x += bv.x; v01.y += bv.y;
                v23.x += bv.x; v23.y += bv.y;
            }
            if (EPI & 4) {
                v01.x = gelu_exact(v01.x); v01.y = gelu_exact(v01.y);
                v23.x = gelu_exact(v23.x); v23.y = gelu_exact(v23.y);
            }
            size_t off0 = (size_t)r0 * ldc + c;
            size_t off1 = (size_t)(r0 + 8) * ldc + c;
            if (EPI & 2) {
                float2 q0 = *(const float2*)(res + off0);
                float2 q1 = *(const float2*)(res + off1);
                v01.x += q0.x; v01.y += q0.y;
                v23.x += q1.x; v23.y += q1.y;
            }
            if constexpr (sizeof(OT) == 2) {
                *(__half2*)((__half*)C + off0) = __floats2half2_rn(v01.x, v01.y);
                *(__half2*)((__half*)C + off1) = __floats2half2_rn(v23.x, v23.y);
            } else {
                *(float2*)((float*)C + off0) = v01;
                *(float2*)((float*)C + off1) = v23;
            }
        }
    }
}

// ---------------------------------------------------------------------------
// Sequential MPS recurrence over fp16 M. One WARP per (b,h) chain.
// Lane j owns its private row; h broadcast via shuffles inside the FMA loop
// (no STS/LDS/syncwarp on the serial path); next row fetched to registers
// and unpacked during the current step. 8-stage cp.async prefetch.
// ---------------------------------------------------------------------------
__global__ void __launch_bounds__(32, 1) recurrence_kernel(
    const __half* __restrict__ Mg, __half* __restrict__ hs)
{
    __shared__ __align__(16) __half smh[8][32][40];
    const int j = threadIdx.x;
    const int b = blockIdx.x >> 4;
    const int h = blockIdx.x & 15;
    const __half* Mbh = Mg + ((size_t)h * BSROWS + (size_t)b * SEQ) * 1024;
    const uint32_t sbase = smem_u32(&smh[0][0][0]) + (uint32_t)j * 80;

    // preload tiles 0..6 into stages 0..6 (one group each)
#pragma unroll
    for (int t = 0; t < 7; t++) {
        const __half* src = Mbh + (size_t)t * 1024 + j * 32;
        const uint32_t dst = sbase + (uint32_t)t * 2560;
#pragma unroll
        for (int c = 0; c < 4; c++) cp16(dst + c * 16, src + c * 8);
        asm volatile("cp.async.commit_group;");
    }
    asm volatile("cp.async.wait_group 6;");   // stage 0 complete

    // load + unpack row for s=0
    float curf[32];
    {
        const uint4* p = (const uint4*)&smh[0][j][0];
        uint4 qq[4] = {p[0], p[1], p[2], p[3]};
        const __half2* h2 = (const __half2*)qq;
#pragma unroll
        for (int c = 0; c < 16; c++) {
            float2 f = __half22float2(h2[c]);
            curf[2 * c] = f.x; curf[2 * c + 1] = f.y;
        }
    }

    float r = 0.17677669529663688f;   // 1/sqrt(32)
    __half* hsb = hs + ((size_t)b * SEQ) * 512 + h * 32 + j;

    for (int s = 0; s < SEQ; ++s) {
        // prefetch tile s+7 into its stage
        if (s + 7 < SEQ) {
            const __half* src = Mbh + (size_t)(s + 7) * 1024 + j * 32;
            const uint32_t dst = sbase + (uint32_t)((s + 7) & 7) * 2560;
#pragma unroll
            for (int c = 0; c < 4; c++) cp16(dst + c * 16, src + c * 8);
        }
        asm volatile("cp.async.commit_group;");
        asm volatile("cp.async.wait_group 6;");   // stage s+1 complete

        // fetch next row to registers (off the serial path)
        uint4 np[4];
        if (s + 1 < SEQ) {
            const uint4* p = (const uint4*)&smh[(s + 1) & 7][j][0];
            np[0] = p[0]; np[1] = p[1]; np[2] = p[2]; np[3] = p[3];
        }

        // serial core: shuffle-broadcast h, fp32 FMA, tanh
        float a0 = 0.f, a1 = 0.f, a2 = 0.f, a3 = 0.f;
#pragma unroll
        for (int i = 0; i < 32; i += 4) {
            a0 = fmaf(__shfl_sync(0xffffffffu, r, i + 0), curf[i + 0], a0);
            a1 = fmaf(__shfl_sync(0xffffffffu, r, i + 1), curf[i + 1], a1);
            a2 = fmaf(__shfl_sync(0xffffffffu, r, i + 2), curf[i + 2], a2);
            a3 = fmaf(__shfl_sync(0xffffffffu, r, i + 3), curf[i + 3], a3);
        }
        r = tanh_fast((a0 + a1) + (a2 + a3));
        hsb[(size_t)s * 512] = __float2half(r);

        // unpack next row into curf (off the serial path)
        if (s + 1 < SEQ) {
            const __half2* h2 = (const __half2*)np;
#pragma unroll
            for (int c = 0; c < 16; c++) {
                float2 f = __half22float2(h2[c]);
                curf[2 * c] = f.x; curf[2 * c + 1] = f.y;
            }
        }
    }
}

// ---------------------------------------------------------------------------
// Launch
// ---------------------------------------------------------------------------
extern "C" void kernel_launch(void* const* d_in, const int* in_sizes, int n_in,
                              void* d_out, int out_size)
{
    const float* x     = (const float*)d_in[0];
    const float* ln1_g = (const float*)d_in[1];
    const float* ln1_b = (const float*)d_in[2];
    const float* W_in  = (const float*)d_in[3];
    const float* b_in  = (const float*)d_in[4];
    const float* A     = (const float*)d_in[5];
    const float* W_out = (const float*)d_in[6];
    const float* b_out = (const float*)d_in[7];
    const float* ln2_g = (const float*)d_in[8];
    const float* ln2_b = (const float*)d_in[9];
    const float* W1    = (const float*)d_in[10];
    const float* b1    = (const float*)d_in[11];
    const float* W2    = (const float*)d_in[12];
    const float* b2    = (const float*)d_in[13];
    float* out = (float*)d_out;

    float *x2;
    __half *lnh, *vh, *a2h, *Mh, *hsh, *ffnh, *winh, *wouth, *w1h, *w2h;
    cudaGetSymbolAddress((void**)&lnh,   g_lnh);
    cudaGetSymbolAddress((void**)&vh,    g_vh);
    cudaGetSymbolAddress((void**)&a2h,   g_a2h);
    cudaGetSymbolAddress((void**)&Mh,    g_Mh);
    cudaGetSymbolAddress((void**)&hsh,   g_hsh);
    cudaGetSymbolAddress((void**)&x2,    g_x2);
    cudaGetSymbolAddress((void**)&ffnh,  g_ffnh);
    cudaGetSymbolAddress((void**)&winh,  g_winh);
    cudaGetSymbolAddress((void**)&wouth, g_wouth);
    cudaGetSymbolAddress((void**)&w1h,   g_w1h);
    cudaGetSymbolAddress((void**)&w2h,   g_w2h);

    cudaFuncSetAttribute((const void*)(hgemm<0, __half>), cudaFuncAttributeMaxDynamicSharedMemorySize, HSMEM_BYTES);
    cudaFuncSetAttribute((const void*)(hgemm<1, __half>), cudaFuncAttributeMaxDynamicSharedMemorySize, HSMEM_BYTES);
    cudaFuncSetAttribute((const void*)(hgemm<5, __half>), cudaFuncAttributeMaxDynamicSharedMemorySize, HSMEM_BYTES);
    cudaFuncSetAttribute((const void*)(hgemm<3, float>),  cudaFuncAttributeMaxDynamicSharedMemorySize, HSMEM_BYTES);

    // 1) A rearrange -> fp16
    prep_A_kernel<<<4096, 256>>>(A, a2h);

    // 2) all weight transposes -> fp16 [N][K]
    tconv_all_kernel<<<9728, dim3(32, 8)>>>(W1, w1h, W2, w2h, W_in, winh, W_out, wouth);

    // 3) LN1 -> fp16
    ln_h_kernel<<<BSROWS, 256>>>(x, ln1_g, ln1_b, lnh);

    // 4) v = ln @ W_in + b_in   [8192 x 1024 x 1024]  fp16 out
    hgemm<1, __half><<<dim3(8, 64, 1), 256, HSMEM_BYTES>>>(
        lnh, winh, vh, b_in, nullptr, DIM, DIM, DIM, DIM, 0, 0, 0);

    // 5) M[h] = v[:, h*64:(h+1)*64] @ A2[h]^T   16 heads, [8192 x 1024 x 64]
    hgemm<0, __half><<<dim3(8, 64, NH), 256, HSMEM_BYTES>>>(
        vh, a2h, Mh, nullptr, nullptr, 64, DIM, 64, 1024,
        (size_t)64, (size_t)65536, (size_t)BSROWS * 1024);

    // 6) sequential recurrence -> hs (fp16)
    recurrence_kernel<<<64, 32>>>(Mh, hsh);

    // 7) x2 = x + hs @ W_out + b_out   [8192 x 1024 x 512]  fp32 out
    hgemm<3, float><<<dim3(8, 64, 1), 256, HSMEM_BYTES>>>(
        hsh, wouth, x2, b_out, x, 512, 512, 512, DIM, 0, 0, 0);

    // 8) LN2 -> fp16
    ln_h_kernel<<<BSROWS, 256>>>(x2, ln2_g, ln2_b, lnh);

    // 9) ffn = gelu(lnh @ W1 + b1)  [8192 x 4096 x 1024]  fp16 out
    hgemm<5, __half><<<dim3(32, 64, 1), 256, HSMEM_BYTES>>>(
        lnh, w1h, ffnh, b1, nullptr, DIM, DIM, DIM, DFF, 0, 0, 0);

    // 10) out = x2 + ffnh @ W2 + b2  [8192 x 1024 x 4096]  fp32 out
    hgemm<3, float><<<dim3(8, 64, 1), 256, HSMEM_BYTES>>>(
        ffnh, w2h, out, b2, x2, DFF, DFF, DFF, DIM, 0, 0, 0);
}

// round 13
// speedup vs baseline: 1.0833x; 1.0833x over previous
#include <cuda_runtime.h>
#include <cuda_fp16.h>
#include <math.h>
#include <cstdint>

#define BSROWS 8192
#define SEQ    2048
#define DIM    1024
#define NH     16
#define DFF    4096

// ---------------------------------------------------------------------------
// Scratch (device globals)
// ---------------------------------------------------------------------------
__device__ __half g_lnh  [8388608];    // LN output (reused LN1/LN2)
__device__ __half g_vh   [8388608];    // v = LN1@W_in + b_in
__device__ __half g_a2h  [1048576];    // A rearranged [h][j*32+i][p]
__device__ __half g_Mh   [134217728];  // M[h][bs][j*32+i]   (268MB)
__device__ __half g_hsh  [4194304];    // recurrence out [bs][H*DH]
__device__ float  g_x2   [8388608];    // x + hs@W_out + b_out (fp32 residual)
__device__ __half g_ffnh [33554432];   // GELU(LN2@W1+b1)
__device__ __half g_winh [1048576];    // W_in^T  [1024][1024]
__device__ __half g_wouth[524288];     // W_out^T [1024][512]
__device__ __half g_w1h  [4194304];    // W1^T    [4096][1024]
__device__ __half g_w2h  [4194304];    // W2^T    [1024][4096]

// ---------------------------------------------------------------------------
// Helpers
// ---------------------------------------------------------------------------
__device__ __forceinline__ uint32_t smem_u32(const void* p) {
    return (uint32_t)__cvta_generic_to_shared(p);
}
__device__ __forceinline__ float gelu_exact(float x) {
    return 0.5f * x * (1.0f + erff(x * 0.70710678118654752f));
}
__device__ __forceinline__ void cp16(uint32_t dst, const void* src) {
    asm volatile("cp.async.cg.shared.global [%0], [%1], 16;" :: "r"(dst), "l"(src));
}
__device__ __forceinline__ float tanh_fast(float x) {
    float r;
    asm("tanh.approx.f32 %0, %1;" : "=f"(r) : "f"(x));
    return r;
}
__device__ __forceinline__ void mma_f16(float* d, const uint32_t* a, const uint32_t* b) {
    asm volatile(
        "mma.sync.aligned.m16n8k16.row.col.f32.f16.f16.f32 "
        "{%0,%1,%2,%3}, {%4,%5,%6,%7}, {%8,%9}, {%0,%1,%2,%3};"
        : "+f"(d[0]), "+f"(d[1]), "+f"(d[2]), "+f"(d[3])
        : "r"(a[0]), "r"(a[1]), "r"(a[2]), "r"(a[3]),
          "r"(b[0]), "r"(b[1]));
}
__device__ __forceinline__ void ldsm4(uint32_t& r0, uint32_t& r1, uint32_t& r2,
                                      uint32_t& r3, uint32_t addr) {
    asm volatile("ldmatrix.sync.aligned.m8n8.x4.shared.b16 {%0,%1,%2,%3}, [%4];"
                 : "=r"(r0), "=r"(r1), "=r"(r2), "=r"(r3) : "r"(addr));
}

// ---------------------------------------------------------------------------
// prep: A[h][i][p][j] -> a2h[h][j*32+i][p]  (fp16)
// ---------------------------------------------------------------------------
__global__ void prep_A_kernel(const float* __restrict__ A, __half* __restrict__ A2) {
    int idx = blockIdx.x * 256 + threadIdx.x;
    int j = idx & 31;
    int p = (idx >> 5) & 63;
    int i = (idx >> 11) & 31;
    int h = idx >> 16;
    A2[(size_t)h * 65536 + (size_t)(j * 32 + i) * 64 + p] = __float2half(A[idx]);
}

// ---------------------------------------------------------------------------
// Merged weight transposes (fp32 [R][C] -> fp16 [C][R]).
// ---------------------------------------------------------------------------
__device__ __forceinline__ void ttile(const float* __restrict__ in,
                                      __half* __restrict__ out,
                                      int R, int C, int bx, int by) {
    __shared__ float t[32][33];
    int tx = threadIdx.x, ty = threadIdx.y;
    int x0 = bx * 32, y0 = by * 32;
#pragma unroll
    for (int j = 0; j < 32; j += 8)
        t[ty + j][tx] = in[(size_t)(y0 + ty + j) * C + x0 + tx];
    __syncthreads();
#pragma unroll
    for (int j = 0; j < 32; j += 8)
        out[(size_t)(x0 + ty + j) * R + y0 + tx] = __float2half(t[tx][ty + j]);
}

__global__ void tconv_all_kernel(const float* __restrict__ W1, __half* __restrict__ w1h,
                                 const float* __restrict__ W2, __half* __restrict__ w2h,
                                 const float* __restrict__ Wi, __half* __restrict__ wih,
                                 const float* __restrict__ Wo, __half* __restrict__ woh)
{
    int t = blockIdx.x;
    if (t < 4096)        ttile(W1, w1h, 1024, 4096, t & 127, t >> 7);
    else if (t < 8192)   { t -= 4096; ttile(W2, w2h, 4096, 1024, t & 31, t >> 5); }
    else if (t < 9216)   { t -= 8192; ttile(Wi, wih, 1024, 1024, t & 31, t >> 5); }
    else                 { t -= 9216; ttile(Wo, woh, 512, 1024, t & 31, t >> 5); }
}

// ---------------------------------------------------------------------------
// LayerNorm (fp32 in, fp16 out).
// ---------------------------------------------------------------------------
__global__ void ln_h_kernel(const float* __restrict__ x, const float* __restrict__ g,
                            const float* __restrict__ b, __half* __restrict__ y) {
    int row = blockIdx.x;
    int tid = threadIdx.x;
    const float* xr = x + (size_t)row * DIM;
    float v[4];
    float s = 0.f, sq = 0.f;
#pragma unroll
    for (int i = 0; i < 4; i++) {
        v[i] = xr[tid + i * 256];
        s  += v[i];
        sq += v[i] * v[i];
    }
#pragma unroll
    for (int o = 16; o > 0; o >>= 1) {
        s  += __shfl_xor_sync(0xffffffffu, s,  o);
        sq += __shfl_xor_sync(0xffffffffu, sq, o);
    }
    __shared__ float ss[8], sqq[8];
    int w = tid >> 5, l = tid & 31;
    if (l == 0) { ss[w] = s; sqq[w] = sq; }
    __syncthreads();
    if (w == 0) {
        s  = (l < 8) ? ss[l]  : 0.f;
        sq = (l < 8) ? sqq[l] : 0.f;
#pragma unroll
        for (int o = 4; o > 0; o >>= 1) {
            s  += __shfl_xor_sync(0xffffffffu, s,  o);
            sq += __shfl_xor_sync(0xffffffffu, sq, o);
        }
        if (l == 0) { ss[0] = s; sqq[0] = sq; }
    }
    __syncthreads();
    s = ss[0]; sq = sqq[0];
    float mean = s * (1.0f / DIM);
    float var  = sq * (1.0f / DIM) - mean * mean;
    float rstd = rsqrtf(var + 1e-5f);
    __half* yr = y + (size_t)row * DIM;
#pragma unroll
    for (int i = 0; i < 4; i++) {
        int c = tid + i * 256;
        yr[c] = __float2half((v[i] - mean) * rstd * g[c] + b[c]);
    }
}

// ---------------------------------------------------------------------------
// fp16 warp-MMA GEMM — R10 configuration (best measured): BK=32, 3-stage
// cp.async, ldmatrix fragments. C[M,N] = A[M,K] @ BT[N,K]^T, fp32 accum.
// CTA 128x128, 8 warps (64x32), mma.m16n8k16.
// SMEM [3][128][40] halves each for A and B (stride 40 -> conflict-free).
// EPI: bit0=bias, bit1=residual(float), bit2=gelu.  OT: __half or float.
// ---------------------------------------------------------------------------
#define HSMEM_BYTES 61440

template <int EPI, typename OT>
__global__ void __launch_bounds__(256, 2) hgemm(
    const __half* __restrict__ A, const __half* __restrict__ BT, OT* __restrict__ C,
    const float* __restrict__ bias, const float* __restrict__ res,
    int K, int lda, int ldb, int ldc,
    size_t batchA, size_t batchB, size_t batchC)
{
    extern __shared__ __half hsm[];
    __half* As = hsm;            // [3][128][40]
    __half* Bs = hsm + 15360;    // [3][128][40]

    A  += (size_t)blockIdx.z * batchA;
    BT += (size_t)blockIdx.z * batchB;
    C  += (size_t)blockIdx.z * batchC;

    const int tid = threadIdx.x;
    const int m0 = blockIdx.y * 128, n0 = blockIdx.x * 128;
    const int wid = tid >> 5, lane = tid & 31;
    const int wm = (wid >> 2) * 64;
    const int wn = (wid & 3) * 32;
    const int gq = lane >> 2, tg = lane & 3;

    const uint32_t sA = smem_u32(As);
    const uint32_t sB = smem_u32(Bs);

    const int row = tid >> 1, half = tid & 1;   // gmem->smem: 2 thr per 64B row

    auto loadA = [&](int st, int k0) {
        const __half* src = A + (size_t)(m0 + row) * lda + k0 + half * 16;
        uint32_t dst = sA + (uint32_t)st * 10240 + (uint32_t)row * 80 + (uint32_t)half * 32;
        cp16(dst, src); cp16(dst + 16, src + 8);
    };
    auto loadB = [&](int st, int k0) {
        const __half* src = BT + (size_t)(n0 + row) * ldb + k0 + half * 16;
        uint32_t dst = sB + (uint32_t)st * 10240 + (uint32_t)row * 80 + (uint32_t)half * 32;
        cp16(dst, src); cp16(dst + 16, src + 8);
    };

    // ldmatrix per-lane byte offsets (within a stage)
    const int arow_l = (lane & 7) | (((lane >> 3) & 1) << 3);  // 0..15
    const int aseg   = lane >> 4;                              // 0/1 (k half)
    const uint32_t aoffB = (uint32_t)(wm + arow_l) * 80 + (uint32_t)aseg * 16;
    const int brow_l = (lane & 7) + ((lane >> 4) << 3);        // 0..15
    const int bseg   = (lane >> 3) & 1;                        // 0/1 (k half)
    const uint32_t boffB = (uint32_t)(wn + brow_l) * 80 + (uint32_t)bseg * 16;

    float acc[4][4][4];
#pragma unroll
    for (int mi = 0; mi < 4; mi++)
#pragma unroll
        for (int ni = 0; ni < 4; ni++)
#pragma unroll
            for (int q = 0; q < 4; q++) acc[mi][ni][q] = 0.f;

    const int KT = K >> 5;
    loadA(0, 0);  loadB(0, 0);
    asm volatile("cp.async.commit_group;");
    loadA(1, 32); loadB(1, 32);
    asm volatile("cp.async.commit_group;");

    for (int kt = 0; kt < KT; ++kt) {
        const int buf = kt % 3;
        asm volatile("cp.async.wait_group 1;");
        __syncthreads();
        if (kt + 2 < KT) {
            const int st = (kt + 2) % 3;
            loadA(st, (kt + 2) * 32);
            loadB(st, (kt + 2) * 32);
        }
        asm volatile("cp.async.commit_group;");

        const uint32_t aB = sA + (uint32_t)buf * 10240 + aoffB;
        const uint32_t bB = sB + (uint32_t)buf * 10240 + boffB;
#pragma unroll
        for (int kk = 0; kk < 32; kk += 16) {
            uint32_t a[4][4], b[4][2];
#pragma unroll
            for (int mi = 0; mi < 4; mi++)
                ldsm4(a[mi][0], a[mi][1], a[mi][2], a[mi][3],
                      aB + (uint32_t)mi * (16 * 80) + (uint32_t)kk * 2);
#pragma unroll
            for (int p = 0; p < 2; p++)
                ldsm4(b[2 * p][0], b[2 * p][1], b[2 * p + 1][0], b[2 * p + 1][1],
                      bB + (uint32_t)p * (16 * 80) + (uint32_t)kk * 2);
#pragma unroll
            for (int mi = 0; mi < 4; mi++)
#pragma unroll
                for (int ni = 0; ni < 4; ni++)
                    mma_f16(acc[mi][ni], a[mi], b[ni]);
        }
    }

    // epilogue
#pragma unroll
    for (int mi = 0; mi < 4; mi++) {
        const int r0 = m0 + wm + mi * 16 + gq;
#pragma unroll
        for (int ni = 0; ni < 4; ni++) {
            const int c = n0 + wn + ni * 8 + 2 * tg;
            float2 v01 = make_float2(acc[mi][ni][0], acc[mi][ni][1]);
            float2 v23 = make_float2(acc[mi][ni][2], acc[mi][ni][3]);
            if (EPI & 1) {
                float2 bv = *(const float2*)(bias + c);
                v01.x += bv.x; v01.y += bv.y;
                v23.x += bv.x; v23.y += bv.y;
            }
            if (EPI & 4) {
                v01.x = gelu_exact(v01.x); v01.y = gelu_exact(v01.y);
                v23.x = gelu_exact(v23.x); v23.y = gelu_exact(v23.y);
            }
            size_t off0 = (size_t)r0 * ldc + c;
            size_t off1 = (size_t)(r0 + 8) * ldc + c;
            if (EPI & 2) {
                float2 q0 = *(const float2*)(res + off0);
                float2 q1 = *(const float2*)(res + off1);
                v01.x += q0.x; v01.y += q0.y;
                v23.x += q1.x; v23.y += q1.y;
            }
            if constexpr (sizeof(OT) == 2) {
                *(__half2*)((__half*)C + off0) = __floats2half2_rn(v01.x, v01.y);
                *(__half2*)((__half*)C + off1) = __floats2half2_rn(v23.x, v23.y);
            } else {
                *(float2*)((float*)C + off0) = v01;
                *(float2*)((float*)C + off1) = v23;
            }
        }
    }
}

// ---------------------------------------------------------------------------
// Sequential MPS recurrence — R12 version (correctness-proven): one WARP per
// (b,h) chain; lane j owns its private row; h broadcast via shuffles inside
// the FMA loop (no STS/LDS/syncwarp on the serial path); next row staged to
// registers during the current step. 8-stage cp.async prefetch.
// ---------------------------------------------------------------------------
__global__ void __launch_bounds__(32, 1) recurrence_kernel(
    const __half* __restrict__ Mg, __half* __restrict__ hs)
{
    __shared__ __align__(16) __half smh[8][32][40];
    const int j = threadIdx.x;
    const int b = blockIdx.x >> 4;
    const int h = blockIdx.x & 15;
    const __half* Mbh = Mg + ((size_t)h * BSROWS + (size_t)b * SEQ) * 1024;
    const uint32_t sbase = smem_u32(&smh[0][0][0]) + (uint32_t)j * 80;

    // preload tiles 0..6 into stages 0..6 (one group each)
#pragma unroll
    for (int t = 0; t < 7; t++) {
        const __half* src = Mbh + (size_t)t * 1024 + j * 32;
        const uint32_t dst = sbase + (uint32_t)t * 2560;
#pragma unroll
        for (int c = 0; c < 4; c++) cp16(dst + c * 16, src + c * 8);
        asm volatile("cp.async.commit_group;");
    }
    asm volatile("cp.async.wait_group 6;");   // stage 0 complete

    // load + unpack row for s=0
    float curf[32];
    {
        const uint4* p = (const uint4*)&smh[0][j][0];
        uint4 qq[4] = {p[0], p[1], p[2], p[3]};
        const __half2* h2 = (const __half2*)qq;
#pragma unroll
        for (int c = 0; c < 16; c++) {
            float2 f = __half22float2(h2[c]);
            curf[2 * c] = f.x; curf[2 * c + 1] = f.y;
        }
    }

    float r = 0.17677669529663688f;   // 1/sqrt(32)
    __half* hsb = hs + ((size_t)b * SEQ) * 512 + h * 32 + j;

    for (int s = 0; s < SEQ; ++s) {
        // prefetch tile s+7 into its stage
        if (s + 7 < SEQ) {
            const __half* src = Mbh + (size_t)(s + 7) * 1024 + j * 32;
            const uint32_t dst = sbase + (uint32_t)((s + 7) & 7) * 2560;
#pragma unroll
            for (int c = 0; c < 4; c++) cp16(dst + c * 16, src + c * 8);
        }
        asm volatile("cp.async.commit_group;");
        asm volatile("cp.async.wait_group 6;");   // stage s+1 complete

        // fetch next row to registers (off the serial path)
        uint4 np[4];
        if (s + 1 < SEQ) {
            const uint4* p = (const uint4*)&smh[(s + 1) & 7][j][0];
            np[0] = p[0]; np[1] = p[1]; np[2] = p[2]; np[3] = p[3];
        }

        // serial core: shuffle-broadcast h, fp32 FMA, tanh
        float a0 = 0.f, a1 = 0.f, a2 = 0.f, a3 = 0.f;
#pragma unroll
        for (int i = 0; i < 32; i += 4) {
            a0 = fmaf(__shfl_sync(0xffffffffu, r, i + 0), curf[i + 0], a0);
            a1 = fmaf(__shfl_sync(0xffffffffu, r, i + 1), curf[i + 1], a1);
            a2 = fmaf(__shfl_sync(0xffffffffu, r, i + 2), curf[i + 2], a2);
            a3 = fmaf(__shfl_sync(0xffffffffu, r, i + 3), curf[i + 3], a3);
        }
        r = tanh_fast((a0 + a1) + (a2 + a3));
        hsb[(size_t)s * 512] = __float2half(r);

        // unpack next row into curf (off the serial path)
        if (s + 1 < SEQ) {
            const __half2* h2 = (const __half2*)np;
#pragma unroll
            for (int c = 0; c < 16; c++) {
                float2 f = __half22float2(h2[c]);
                curf[2 * c] = f.x; curf[2 * c + 1] = f.y;
            }
        }
    }
}

// ---------------------------------------------------------------------------
// Launch
// ---------------------------------------------------------------------------
extern "C" void kernel_launch(void* const* d_in, const int* in_sizes, int n_in,
                              void* d_out, int out_size)
{
    const float* x     = (const float*)d_in[0];
    const float* ln1_g = (const float*)d_in[1];
    const float* ln1_b = (const float*)d_in[2];
    const float* W_in  = (const float*)d_in[3];
    const float* b_in  = (const float*)d_in[4];
    const float* A     = (const float*)d_in[5];
    const float* W_out = (const float*)d_in[6];
    const float* b_out = (const float*)d_in[7];
    const float* ln2_g = (const float*)d_in[8];
    const float* ln2_b = (const float*)d_in[9];
    const float* W1    = (const float*)d_in[10];
    const float* b1    = (const float*)d_in[11];
    const float* W2    = (const float*)d_in[12];
    const float* b2    = (const float*)d_in[13];
    float* out = (float*)d_out;

    float *x2;
    __half *lnh, *vh, *a2h, *Mh, *hsh, *ffnh, *winh, *wouth, *w1h, *w2h;
    cudaGetSymbolAddress((void**)&lnh,   g_lnh);
    cudaGetSymbolAddress((void**)&vh,    g_vh);
    cudaGetSymbolAddress((void**)&a2h,   g_a2h);
    cudaGetSymbolAddress((void**)&Mh,    g_Mh);
    cudaGetSymbolAddress((void**)&hsh,   g_hsh);
    cudaGetSymbolAddress((void**)&x2,    g_x2);
    cudaGetSymbolAddress((void**)&ffnh,  g_ffnh);
    cudaGetSymbolAddress((void**)&winh,  g_winh);
    cudaGetSymbolAddress((void**)&wouth, g_wouth);
    cudaGetSymbolAddress((void**)&w1h,   g_w1h);
    cudaGetSymbolAddress((void**)&w2h,   g_w2h);

    cudaFuncSetAttribute((const void*)(hgemm<0, __half>), cudaFuncAttributeMaxDynamicSharedMemorySize, HSMEM_BYTES);
    cudaFuncSetAttribute((const void*)(hgemm<1, __half>), cudaFuncAttributeMaxDynamicSharedMemorySize, HSMEM_BYTES);
    cudaFuncSetAttribute((const void*)(hgemm<5, __half>), cudaFuncAttributeMaxDynamicSharedMemorySize, HSMEM_BYTES);
    cudaFuncSetAttribute((const void*)(hgemm<3, float>),  cudaFuncAttributeMaxDynamicSharedMemorySize, HSMEM_BYTES);

    // 1) A rearrange -> fp16
    prep_A_kernel<<<4096, 256>>>(A, a2h);

    // 2) all weight transposes -> fp16 [N][K]
    tconv_all_kernel<<<9728, dim3(32, 8)>>>(W1, w1h, W2, w2h, W_in, winh, W_out, wouth);

    // 3) LN1 -> fp16
    ln_h_kernel<<<BSROWS, 256>>>(x, ln1_g, ln1_b, lnh);

    // 4) v = ln @ W_in + b_in   [8192 x 1024 x 1024]  fp16 out
    hgemm<1, __half><<<dim3(8, 64, 1), 256, HSMEM_BYTES>>>(
        lnh, winh, vh, b_in, nullptr, DIM, DIM, DIM, DIM, 0, 0, 0);

    // 5) M[h] = v[:, h*64:(h+1)*64] @ A2[h]^T   16 heads, [8192 x 1024 x 64]
    hgemm<0, __half><<<dim3(8, 64, NH), 256, HSMEM_BYTES>>>(
        vh, a2h, Mh, nullptr, nullptr, 64, DIM, 64, 1024,
        (size_t)64, (size_t)65536, (size_t)BSROWS * 1024);

    // 6) sequential recurrence -> hs (fp16)
    recurrence_kernel<<<64, 32>>>(Mh, hsh);

    // 7) x2 = x + hs @ W_out + b_out   [8192 x 1024 x 512]  fp32 out
    hgemm<3, float><<<dim3(8, 64, 1), 256, HSMEM_BYTES>>>(
        hsh, wouth, x2, b_out, x, 512, 512, 512, DIM, 0, 0, 0);

    // 8) LN2 -> fp16
    ln_h_kernel<<<BSROWS, 256>>>(x2, ln2_g, ln2_b, lnh);

    // 9) ffn = gelu(lnh @ W1 + b1)  [8192 x 4096 x 1024]  fp16 out
    hgemm<5, __half><<<dim3(32, 64, 1), 256, HSMEM_BYTES>>>(
        lnh, w1h, ffnh, b1, nullptr, DIM, DIM, DIM, DFF, 0, 0, 0);

    // 10) out = x2 + ffnh @ W2 + b2  [8192 x 1024 x 4096]  fp32 out
    hgemm<3, float><<<dim3(8, 64, 1), 256, HSMEM_BYTES>>>(
        ffnh, w2h, out, b2, x2, DFF, DFF, DFF, DIM, 0, 0, 0);
}

// round 14
// speedup vs baseline: 1.1587x; 1.0696x over previous
#include <cuda_runtime.h>
#include <cuda_fp16.h>
#include <math.h>
#include <cstdint>

#define BSROWS 8192
#define SEQ    2048
#define DIM    1024
#define NH     16
#define DFF    4096

// ---------------------------------------------------------------------------
// Scratch (device globals)
// ---------------------------------------------------------------------------
__device__ __half g_lnh  [8388608];    // LN output (reused LN1/LN2)
__device__ __half g_vh   [8388608];    // v = LN1@W_in + b_in
__device__ __half g_a2h  [1048576];    // A rearranged [h][j*32+i][p]
__device__ __half g_Mh   [134217728];  // M[h][bs][j*32+i]   (268MB)
__device__ __half g_hsh  [4194304];    // recurrence out [bs][H*DH]
__device__ float  g_x2   [8388608];    // x + hs@W_out + b_out (fp32 residual)
__device__ __half g_ffnh [33554432];   // GELU(LN2@W1+b1)
__device__ __half g_winh [1048576];    // W_in^T  [1024][1024]
__device__ __half g_wouth[524288];     // W_out^T [1024][512]
__device__ __half g_w1h  [4194304];    // W1^T    [4096][1024]
__device__ __half g_w2h  [4194304];    // W2^T    [1024][4096]

// ---------------------------------------------------------------------------
// Helpers
// ---------------------------------------------------------------------------
__device__ __forceinline__ uint32_t smem_u32(const void* p) {
    return (uint32_t)__cvta_generic_to_shared(p);
}
__device__ __forceinline__ float gelu_exact(float x) {
    return 0.5f * x * (1.0f + erff(x * 0.70710678118654752f));
}
__device__ __forceinline__ void cp16(uint32_t dst, const void* src) {
    asm volatile("cp.async.cg.shared.global [%0], [%1], 16;" :: "r"(dst), "l"(src));
}
__device__ __forceinline__ float tanh_fast(float x) {
    float r;
    asm("tanh.approx.f32 %0, %1;" : "=f"(r) : "f"(x));
    return r;
}
__device__ __forceinline__ void mma_f16(float* d, const uint32_t* a, const uint32_t* b) {
    asm volatile(
        "mma.sync.aligned.m16n8k16.row.col.f32.f16.f16.f32 "
        "{%0,%1,%2,%3}, {%4,%5,%6,%7}, {%8,%9}, {%0,%1,%2,%3};"
        : "+f"(d[0]), "+f"(d[1]), "+f"(d[2]), "+f"(d[3])
        : "r"(a[0]), "r"(a[1]), "r"(a[2]), "r"(a[3]),
          "r"(b[0]), "r"(b[1]));
}
__device__ __forceinline__ void ldsm4(uint32_t& r0, uint32_t& r1, uint32_t& r2,
                                      uint32_t& r3, uint32_t addr) {
    asm volatile("ldmatrix.sync.aligned.m8n8.x4.shared.b16 {%0,%1,%2,%3}, [%4];"
                 : "=r"(r0), "=r"(r1), "=r"(r2), "=r"(r3) : "r"(addr));
}

// ---------------------------------------------------------------------------
// prep: A[h][i][p][j] -> a2h[h][j*32+i][p]  (fp16)
// ---------------------------------------------------------------------------
__global__ void prep_A_kernel(const float* __restrict__ A, __half* __restrict__ A2) {
    int idx = blockIdx.x * 256 + threadIdx.x;
    int j = idx & 31;
    int p = (idx >> 5) & 63;
    int i = (idx >> 11) & 31;
    int h = idx >> 16;
    A2[(size_t)h * 65536 + (size_t)(j * 32 + i) * 64 + p] = __float2half(A[idx]);
}

// ---------------------------------------------------------------------------
// Merged weight transposes (fp32 [R][C] -> fp16 [C][R]).
// ---------------------------------------------------------------------------
__device__ __forceinline__ void ttile(const float* __restrict__ in,
                                      __half* __restrict__ out,
                                      int R, int C, int bx, int by) {
    __shared__ float t[32][33];
    int tx = threadIdx.x, ty = threadIdx.y;
    int x0 = bx * 32, y0 = by * 32;
#pragma unroll
    for (int j = 0; j < 32; j += 8)
        t[ty + j][tx] = in[(size_t)(y0 + ty + j) * C + x0 + tx];
    __syncthreads();
#pragma unroll
    for (int j = 0; j < 32; j += 8)
        out[(size_t)(x0 + ty + j) * R + y0 + tx] = __float2half(t[tx][ty + j]);
}

__global__ void tconv_all_kernel(const float* __restrict__ W1, __half* __restrict__ w1h,
                                 const float* __restrict__ W2, __half* __restrict__ w2h,
                                 const float* __restrict__ Wi, __half* __restrict__ wih,
                                 const float* __restrict__ Wo, __half* __restrict__ woh)
{
    int t = blockIdx.x;
    if (t < 4096)        ttile(W1, w1h, 1024, 4096, t & 127, t >> 7);
    else if (t < 8192)   { t -= 4096; ttile(W2, w2h, 4096, 1024, t & 31, t >> 5); }
    else if (t < 9216)   { t -= 8192; ttile(Wi, wih, 1024, 1024, t & 31, t >> 5); }
    else                 { t -= 9216; ttile(Wo, woh, 512, 1024, t & 31, t >> 5); }
}

// ---------------------------------------------------------------------------
// LayerNorm (fp32 in, fp16 out).
// ---------------------------------------------------------------------------
__global__ void ln_h_kernel(const float* __restrict__ x, const float* __restrict__ g,
                            const float* __restrict__ b, __half* __restrict__ y) {
    int row = blockIdx.x;
    int tid = threadIdx.x;
    const float* xr = x + (size_t)row * DIM;
    float v[4];
    float s = 0.f, sq = 0.f;
#pragma unroll
    for (int i = 0; i < 4; i++) {
        v[i] = xr[tid + i * 256];
        s  += v[i];
        sq += v[i] * v[i];
    }
#pragma unroll
    for (int o = 16; o > 0; o >>= 1) {
        s  += __shfl_xor_sync(0xffffffffu, s,  o);
        sq += __shfl_xor_sync(0xffffffffu, sq, o);
    }
    __shared__ float ss[8], sqq[8];
    int w = tid >> 5, l = tid & 31;
    if (l == 0) { ss[w] = s; sqq[w] = sq; }
    __syncthreads();
    if (w == 0) {
        s  = (l < 8) ? ss[l]  : 0.f;
        sq = (l < 8) ? sqq[l] : 0.f;
#pragma unroll
        for (int o = 4; o > 0; o >>= 1) {
            s  += __shfl_xor_sync(0xffffffffu, s,  o);
            sq += __shfl_xor_sync(0xffffffffu, sq, o);
        }
        if (l == 0) { ss[0] = s; sqq[0] = sq; }
    }
    __syncthreads();
    s = ss[0]; sq = sqq[0];
    float mean = s * (1.0f / DIM);
    float var  = sq * (1.0f / DIM) - mean * mean;
    float rstd = rsqrtf(var + 1e-5f);
    __half* yr = y + (size_t)row * DIM;
#pragma unroll
    for (int i = 0; i < 4; i++) {
        int c = tid + i * 256;
        yr[c] = __float2half((v[i] - mean) * rstd * g[c] + b[c]);
    }
}

// ---------------------------------------------------------------------------
// fp16 warp-MMA GEMM — R10 configuration (best measured): BK=32, 3-stage
// cp.async, ldmatrix fragments. C[M,N] = A[M,K] @ BT[N,K]^T, fp32 accum.
// CTA 128x128, 8 warps (64x32), mma.m16n8k16.
// SMEM [3][128][40] halves each for A and B (stride 40 -> conflict-free).
// EPI: bit0=bias, bit1=residual(float), bit2=gelu.  OT: __half or float.
// ---------------------------------------------------------------------------
#define HSMEM_BYTES 61440

template <int EPI, typename OT>
__global__ void __launch_bounds__(256, 2) hgemm(
    const __half* __restrict__ A, const __half* __restrict__ BT, OT* __restrict__ C,
    const float* __restrict__ bias, const float* __restrict__ res,
    int K, int lda, int ldb, int ldc,
    size_t batchA, size_t batchB, size_t batchC)
{
    extern __shared__ __half hsm[];
    __half* As = hsm;            // [3][128][40]
    __half* Bs = hsm + 15360;    // [3][128][40]

    A  += (size_t)blockIdx.z * batchA;
    BT += (size_t)blockIdx.z * batchB;
    C  += (size_t)blockIdx.z * batchC;

    const int tid = threadIdx.x;
    const int m0 = blockIdx.y * 128, n0 = blockIdx.x * 128;
    const int wid = tid >> 5, lane = tid & 31;
    const int wm = (wid >> 2) * 64;
    const int wn = (wid & 3) * 32;
    const int gq = lane >> 2, tg = lane & 3;

    const uint32_t sA = smem_u32(As);
    const uint32_t sB = smem_u32(Bs);

    const int row = tid >> 1, half = tid & 1;   // gmem->smem: 2 thr per 64B row

    auto loadA = [&](int st, int k0) {
        const __half* src = A + (size_t)(m0 + row) * lda + k0 + half * 16;
        uint32_t dst = sA + (uint32_t)st * 10240 + (uint32_t)row * 80 + (uint32_t)half * 32;
        cp16(dst, src); cp16(dst + 16, src + 8);
    };
    auto loadB = [&](int st, int k0) {
        const __half* src = BT + (size_t)(n0 + row) * ldb + k0 + half * 16;
        uint32_t dst = sB + (uint32_t)st * 10240 + (uint32_t)row * 80 + (uint32_t)half * 32;
        cp16(dst, src); cp16(dst + 16, src + 8);
    };

    // ldmatrix per-lane byte offsets (within a stage)
    const int arow_l = (lane & 7) | (((lane >> 3) & 1) << 3);  // 0..15
    const int aseg   = lane >> 4;                              // 0/1 (k half)
    const uint32_t aoffB = (uint32_t)(wm + arow_l) * 80 + (uint32_t)aseg * 16;
    const int brow_l = (lane & 7) + ((lane >> 4) << 3);        // 0..15
    const int bseg   = (lane >> 3) & 1;                        // 0/1 (k half)
    const uint32_t boffB = (uint32_t)(wn + brow_l) * 80 + (uint32_t)bseg * 16;

    float acc[4][4][4];
#pragma unroll
    for (int mi = 0; mi < 4; mi++)
#pragma unroll
        for (int ni = 0; ni < 4; ni++)
#pragma unroll
            for (int q = 0; q < 4; q++) acc[mi][ni][q] = 0.f;

    const int KT = K >> 5;
    loadA(0, 0);  loadB(0, 0);
    asm volatile("cp.async.commit_group;");
    loadA(1, 32); loadB(1, 32);
    asm volatile("cp.async.commit_group;");

    for (int kt = 0; kt < KT; ++kt) {
        const int buf = kt % 3;
        asm volatile("cp.async.wait_group 1;");
        __syncthreads();
        if (kt + 2 < KT) {
            const int st = (kt + 2) % 3;
            loadA(st, (kt + 2) * 32);
            loadB(st, (kt + 2) * 32);
        }
        asm volatile("cp.async.commit_group;");

        const uint32_t aB = sA + (uint32_t)buf * 10240 + aoffB;
        const uint32_t bB = sB + (uint32_t)buf * 10240 + boffB;
#pragma unroll
        for (int kk = 0; kk < 32; kk += 16) {
            uint32_t a[4][4], b[4][2];
#pragma unroll
            for (int mi = 0; mi < 4; mi++)
                ldsm4(a[mi][0], a[mi][1], a[mi][2], a[mi][3],
                      aB + (uint32_t)mi * (16 * 80) + (uint32_t)kk * 2);
#pragma unroll
            for (int p = 0; p < 2; p++)
                ldsm4(b[2 * p][0], b[2 * p][1], b[2 * p + 1][0], b[2 * p + 1][1],
                      bB + (uint32_t)p * (16 * 80) + (uint32_t)kk * 2);
#pragma unroll
            for (int mi = 0; mi < 4; mi++)
#pragma unroll
                for (int ni = 0; ni < 4; ni++)
                    mma_f16(acc[mi][ni], a[mi], b[ni]);
        }
    }

    // epilogue
#pragma unroll
    for (int mi = 0; mi < 4; mi++) {
        const int r0 = m0 + wm + mi * 16 + gq;
#pragma unroll
        for (int ni = 0; ni < 4; ni++) {
            const int c = n0 + wn + ni * 8 + 2 * tg;
            float2 v01 = make_float2(acc[mi][ni][0], acc[mi][ni][1]);
            float2 v23 = make_float2(acc[mi][ni][2], acc[mi][ni][3]);
            if (EPI & 1) {
                float2 bv = *(const float2*)(bias + c);
                v01.x += bv.x; v01.y += bv.y;
                v23.x += bv.x; v23.y += bv.y;
            }
            if (EPI & 4) {
                v01.x = gelu_exact(v01.x); v01.y = gelu_exact(v01.y);
                v23.x = gelu_exact(v23.x); v23.y = gelu_exact(v23.y);
            }
            size_t off0 = (size_t)r0 * ldc + c;
            size_t off1 = (size_t)(r0 + 8) * ldc + c;
            if (EPI & 2) {
                float2 q0 = *(const float2*)(res + off0);
                float2 q1 = *(const float2*)(res + off1);
                v01.x += q0.x; v01.y += q0.y;
                v23.x += q1.x; v23.y += q1.y;
            }
            if constexpr (sizeof(OT) == 2) {
                *(__half2*)((__half*)C + off0) = __floats2half2_rn(v01.x, v01.y);
                *(__half2*)((__half*)C + off1) = __floats2half2_rn(v23.x, v23.y);
            } else {
                *(float2*)((float*)C + off0) = v01;
                *(float2*)((float*)C + off1) = v23;
            }
        }
    }
}

// ---------------------------------------------------------------------------
// Sequential MPS recurrence — R10 proven skeleton (h in double-buffered smem,
// inline half2->float2 conversion, one syncwarp/step) with two serial-path
// cuts: packed fma.rn.f32x2 (halves FMA issue count; fp32-exact) and FOUR
// packed accumulators (dependency chain 8 -> 4 deep). 8-stage cp.async
// prefetch, one warp per (b,h) chain.
// ---------------------------------------------------------------------------
__global__ void __launch_bounds__(32, 1) recurrence_kernel(
    const __half* __restrict__ Mg, __half* __restrict__ hs)
{
    __shared__ __align__(16) __half smh[8][32][40];
    __shared__ __align__(16) float hsm[2][32];
    const int j = threadIdx.x;
    const int b = blockIdx.x >> 4;
    const int h = blockIdx.x & 15;
    const __half* Mbh = Mg + ((size_t)h * BSROWS + (size_t)b * SEQ) * 1024;
    const uint32_t sbase = smem_u32(&smh[0][0][0]) + (uint32_t)j * 80;

    // preload tiles 0..6 into stages 0..6 (one commit group each)
#pragma unroll
    for (int t = 0; t < 7; t++) {
        const __half* src = Mbh + (size_t)t * 1024 + j * 32;
        const uint32_t dst = sbase + (uint32_t)t * 2560;
#pragma unroll
        for (int c = 0; c < 4; c++) cp16(dst + c * 16, src + c * 8);
        asm volatile("cp.async.commit_group;");
    }
    hsm[0][j] = 0.17677669529663688f;   // 1/sqrt(32)
    __syncwarp();

    __half* hsb = hs + ((size_t)b * SEQ) * 512 + h * 32 + j;

    for (int s = 0; s < SEQ; ++s) {
        // prefetch tile s+7 into its stage
        if (s + 7 < SEQ) {
            const __half* src = Mbh + (size_t)(s + 7) * 1024 + j * 32;
            const uint32_t dst = sbase + (uint32_t)((s + 7) & 7) * 2560;
#pragma unroll
            for (int c = 0; c < 4; c++) cp16(dst + c * 16, src + c * 8);
        }
        asm volatile("cp.async.commit_group;");
        asm volatile("cp.async.wait_group 7;");   // tile s ready

        const __half2* row2 = (const __half2*)&smh[s & 7][j][0];
        const float*   hv   = hsm[s & 1];
        unsigned long long accA = 0ull, accB = 0ull, accC = 0ull, accD = 0ull;
#pragma unroll
        for (int c = 0; c < 4; c++) {            // 8 i-values per iteration
            ulonglong2 h01 = *(const ulonglong2*)(hv + c * 8);
            ulonglong2 h23 = *(const ulonglong2*)(hv + c * 8 + 4);
            float2 m0 = __half22float2(row2[4 * c + 0]);
            float2 m1 = __half22float2(row2[4 * c + 1]);
            float2 m2 = __half22float2(row2[4 * c + 2]);
            float2 m3 = __half22float2(row2[4 * c + 3]);
            unsigned long long u0 = *(unsigned long long*)&m0;
            unsigned long long u1 = *(unsigned long long*)&m1;
            unsigned long long u2 = *(unsigned long long*)&m2;
            unsigned long long u3 = *(unsigned long long*)&m3;
            asm("fma.rn.f32x2 %0, %1, %2, %0;" : "+l"(accA) : "l"(h01.x), "l"(u0));
            asm("fma.rn.f32x2 %0, %1, %2, %0;" : "+l"(accB) : "l"(h01.y), "l"(u1));
            asm("fma.rn.f32x2 %0, %1, %2, %0;" : "+l"(accC) : "l"(h23.x), "l"(u2));
            asm("fma.rn.f32x2 %0, %1, %2, %0;" : "+l"(accD) : "l"(h23.y), "l"(u3));
        }
        float2 fa = *(float2*)&accA;
        float2 fb = *(float2*)&accB;
        float2 fc = *(float2*)&accC;
        float2 fd = *(float2*)&accD;
        float r = tanh_fast(((fa.x + fa.y) + (fb.x + fb.y)) +
                            ((fc.x + fc.y) + (fd.x + fd.y)));
        hsm[(s + 1) & 1][j] = r;
        hsb[(size_t)s * 512] = __float2half(r);
        __syncwarp();   // h write visible before next step's reads
    }
}

// ---------------------------------------------------------------------------
// Launch
// ---------------------------------------------------------------------------
extern "C" void kernel_launch(void* const* d_in, const int* in_sizes, int n_in,
                              void* d_out, int out_size)
{
    const float* x     = (const float*)d_in[0];
    const float* ln1_g = (const float*)d_in[1];
    const float* ln1_b = (const float*)d_in[2];
    const float* W_in  = (const float*)d_in[3];
    const float* b_in  = (const float*)d_in[4];
    const float* A     = (const float*)d_in[5];
    const float* W_out = (const float*)d_in[6];
    const float* b_out = (const float*)d_in[7];
    const float* ln2_g = (const float*)d_in[8];
    const float* ln2_b = (const float*)d_in[9];
    const float* W1    = (const float*)d_in[10];
    const float* b1    = (const float*)d_in[11];
    const float* W2    = (const float*)d_in[12];
    const float* b2    = (const float*)d_in[13];
    float* out = (float*)d_out;

    float *x2;
    __half *lnh, *vh, *a2h, *Mh, *hsh, *ffnh, *winh, *wouth, *w1h, *w2h;
    cudaGetSymbolAddress((void**)&lnh,   g_lnh);
    cudaGetSymbolAddress((void**)&vh,    g_vh);
    cudaGetSymbolAddress((void**)&a2h,   g_a2h);
    cudaGetSymbolAddress((void**)&Mh,    g_Mh);
    cudaGetSymbolAddress((void**)&hsh,   g_hsh);
    cudaGetSymbolAddress((void**)&x2,    g_x2);
    cudaGetSymbolAddress((void**)&ffnh,  g_ffnh);
    cudaGetSymbolAddress((void**)&winh,  g_winh);
    cudaGetSymbolAddress((void**)&wouth, g_wouth);
    cudaGetSymbolAddress((void**)&w1h,   g_w1h);
    cudaGetSymbolAddress((void**)&w2h,   g_w2h);

    cudaFuncSetAttribute((const void*)(hgemm<0, __half>), cudaFuncAttributeMaxDynamicSharedMemorySize, HSMEM_BYTES);
    cudaFuncSetAttribute((const void*)(hgemm<1, __half>), cudaFuncAttributeMaxDynamicSharedMemorySize, HSMEM_BYTES);
    cudaFuncSetAttribute((const void*)(hgemm<5, __half>), cudaFuncAttributeMaxDynamicSharedMemorySize, HSMEM_BYTES);
    cudaFuncSetAttribute((const void*)(hgemm<3, float>),  cudaFuncAttributeMaxDynamicSharedMemorySize, HSMEM_BYTES);

    // 1) A rearrange -> fp16
    prep_A_kernel<<<4096, 256>>>(A, a2h);

    // 2) all weight transposes -> fp16 [N][K]
    tconv_all_kernel<<<9728, dim3(32, 8)>>>(W1, w1h, W2, w2h, W_in, winh, W_out, wouth);

    // 3) LN1 -> fp16
    ln_h_kernel<<<BSROWS, 256>>>(x, ln1_g, ln1_b, lnh);

    // 4) v = ln @ W_in + b_in   [8192 x 1024 x 1024]  fp16 out
    hgemm<1, __half><<<dim3(8, 64, 1), 256, HSMEM_BYTES>>>(
        lnh, winh, vh, b_in, nullptr, DIM, DIM, DIM, DIM, 0, 0, 0);

    // 5) M[h] = v[:, h*64:(h+1)*64] @ A2[h]^T   16 heads, [8192 x 1024 x 64]
    hgemm<0, __half><<<dim3(8, 64, NH), 256, HSMEM_BYTES>>>(
        vh, a2h, Mh, nullptr, nullptr, 64, DIM, 64, 1024,
        (size_t)64, (size_t)65536, (size_t)BSROWS * 1024);

    // 6) sequential recurrence -> hs (fp16)
    recurrence_kernel<<<64, 32>>>(Mh, hsh);

    // 7) x2 = x + hs @ W_out + b_out   [8192 x 1024 x 512]  fp32 out
    hgemm<3, float><<<dim3(8, 64, 1), 256, HSMEM_BYTES>>>(
        hsh, wouth, x2, b_out, x, 512, 512, 512, DIM, 0, 0, 0);

    // 8) LN2 -> fp16
    ln_h_kernel<<<BSROWS, 256>>>(x2, ln2_g, ln2_b, lnh);

    // 9) ffn = gelu(lnh @ W1 + b1)  [8192 x 4096 x 1024]  fp16 out
    hgemm<5, __half><<<dim3(32, 64, 1), 256, HSMEM_BYTES>>>(
        lnh, w1h, ffnh, b1, nullptr, DIM, DIM, DIM, DFF, 0, 0, 0);

    // 10) out = x2 + ffnh @ W2 + b2  [8192 x 1024 x 4096]  fp32 out
    hgemm<3, float><<<dim3(8, 64, 1), 256, HSMEM_BYTES>>>(
        ffnh, w2h, out, b2, x2, DFF, DFF, DFF, DIM, 0, 0, 0);
}

// round 15
// speedup vs baseline: 1.1951x; 1.0314x over previous
#include <cuda_runtime.h>
#include <cuda_fp16.h>
#include <math.h>
#include <cstdint>

#define BSROWS 8192
#define SEQ    2048
#define DIM    1024
#define NH     16
#define DFF    4096

// ---------------------------------------------------------------------------
// Scratch (device globals)
// ---------------------------------------------------------------------------
__device__ __half g_lnh  [8388608];    // LN output (reused LN1/LN2)
__device__ __half g_vh   [8388608];    // v = LN1@W_in + b_in
__device__ __half g_a2h  [1048576];    // A rearranged [h][j*32+i][p]
__device__ __half g_Mh   [134217728];  // M[h][bs][j*32+i]   (268MB)
__device__ __half g_hsh  [4194304];    // recurrence out [bs][H*DH]
__device__ float  g_x2   [8388608];    // x + hs@W_out + b_out (fp32 residual)
__device__ __half g_ffnh [33554432];   // GELU(LN2@W1+b1)
__device__ __half g_winh [1048576];    // W_in^T  [1024][1024]
__device__ __half g_wouth[524288];     // W_out^T [1024][512]
__device__ __half g_w1h  [4194304];    // W1^T    [4096][1024]
__device__ __half g_w2h  [4194304];    // W2^T    [1024][4096]

// ---------------------------------------------------------------------------
// Helpers
// ---------------------------------------------------------------------------
__device__ __forceinline__ uint32_t smem_u32(const void* p) {
    return (uint32_t)__cvta_generic_to_shared(p);
}
__device__ __forceinline__ float gelu_exact(float x) {
    return 0.5f * x * (1.0f + erff(x * 0.70710678118654752f));
}
__device__ __forceinline__ void cp16(uint32_t dst, const void* src) {
    asm volatile("cp.async.cg.shared.global [%0], [%1], 16;" :: "r"(dst), "l"(src));
}
__device__ __forceinline__ float tanh_fast(float x) {
    float r;
    asm("tanh.approx.f32 %0, %1;" : "=f"(r) : "f"(x));
    return r;
}
__device__ __forceinline__ void mma_f16(float* d, const uint32_t* a, const uint32_t* b) {
    asm volatile(
        "mma.sync.aligned.m16n8k16.row.col.f32.f16.f16.f32 "
        "{%0,%1,%2,%3}, {%4,%5,%6,%7}, {%8,%9}, {%0,%1,%2,%3};"
        : "+f"(d[0]), "+f"(d[1]), "+f"(d[2]), "+f"(d[3])
        : "r"(a[0]), "r"(a[1]), "r"(a[2]), "r"(a[3]),
          "r"(b[0]), "r"(b[1]));
}
__device__ __forceinline__ void ldsm4(uint32_t& r0, uint32_t& r1, uint32_t& r2,
                                      uint32_t& r3, uint32_t addr) {
    asm volatile("ldmatrix.sync.aligned.m8n8.x4.shared.b16 {%0,%1,%2,%3}, [%4];"
                 : "=r"(r0), "=r"(r1), "=r"(r2), "=r"(r3) : "r"(addr));
}

// ---------------------------------------------------------------------------
// prep: A[h][i][p][j] -> a2h[h][j*32+i][p]  (fp16)
// ---------------------------------------------------------------------------
__global__ void prep_A_kernel(const float* __restrict__ A, __half* __restrict__ A2) {
    int idx = blockIdx.x * 256 + threadIdx.x;
    int j = idx & 31;
    int p = (idx >> 5) & 63;
    int i = (idx >> 11) & 31;
    int h = idx >> 16;
    A2[(size_t)h * 65536 + (size_t)(j * 32 + i) * 64 + p] = __float2half(A[idx]);
}

// ---------------------------------------------------------------------------
// Merged weight transposes (fp32 [R][C] -> fp16 [C][R]).
// ---------------------------------------------------------------------------
__device__ __forceinline__ void ttile(const float* __restrict__ in,
                                      __half* __restrict__ out,
                                      int R, int C, int bx, int by) {
    __shared__ float t[32][33];
    int tx = threadIdx.x, ty = threadIdx.y;
    int x0 = bx * 32, y0 = by * 32;
#pragma unroll
    for (int j = 0; j < 32; j += 8)
        t[ty + j][tx] = in[(size_t)(y0 + ty + j) * C + x0 + tx];
    __syncthreads();
#pragma unroll
    for (int j = 0; j < 32; j += 8)
        out[(size_t)(x0 + ty + j) * R + y0 + tx] = __float2half(t[tx][ty + j]);
}

__global__ void tconv_all_kernel(const float* __restrict__ W1, __half* __restrict__ w1h,
                                 const float* __restrict__ W2, __half* __restrict__ w2h,
                                 const float* __restrict__ Wi, __half* __restrict__ wih,
                                 const float* __restrict__ Wo, __half* __restrict__ woh)
{
    int t = blockIdx.x;
    if (t < 4096)        ttile(W1, w1h, 1024, 4096, t & 127, t >> 7);
    else if (t < 8192)   { t -= 4096; ttile(W2, w2h, 4096, 1024, t & 31, t >> 5); }
    else if (t < 9216)   { t -= 8192; ttile(Wi, wih, 1024, 1024, t & 31, t >> 5); }
    else                 { t -= 9216; ttile(Wo, woh, 512, 1024, t & 31, t >> 5); }
}

// ---------------------------------------------------------------------------
// LayerNorm (fp32 in, fp16 out).
// ---------------------------------------------------------------------------
__global__ void ln_h_kernel(const float* __restrict__ x, const float* __restrict__ g,
                            const float* __restrict__ b, __half* __restrict__ y) {
    int row = blockIdx.x;
    int tid = threadIdx.x;
    const float* xr = x + (size_t)row * DIM;
    float v[4];
    float s = 0.f, sq = 0.f;
#pragma unroll
    for (int i = 0; i < 4; i++) {
        v[i] = xr[tid + i * 256];
        s  += v[i];
        sq += v[i] * v[i];
    }
#pragma unroll
    for (int o = 16; o > 0; o >>= 1) {
        s  += __shfl_xor_sync(0xffffffffu, s,  o);
        sq += __shfl_xor_sync(0xffffffffu, sq, o);
    }
    __shared__ float ss[8], sqq[8];
    int w = tid >> 5, l = tid & 31;
    if (l == 0) { ss[w] = s; sqq[w] = sq; }
    __syncthreads();
    if (w == 0) {
        s  = (l < 8) ? ss[l]  : 0.f;
        sq = (l < 8) ? sqq[l] : 0.f;
#pragma unroll
        for (int o = 4; o > 0; o >>= 1) {
            s  += __shfl_xor_sync(0xffffffffu, s,  o);
            sq += __shfl_xor_sync(0xffffffffu, sq, o);
        }
        if (l == 0) { ss[0] = s; sqq[0] = sq; }
    }
    __syncthreads();
    s = ss[0]; sq = sqq[0];
    float mean = s * (1.0f / DIM);
    float var  = sq * (1.0f / DIM) - mean * mean;
    float rstd = rsqrtf(var + 1e-5f);
    __half* yr = y + (size_t)row * DIM;
#pragma unroll
    for (int i = 0; i < 4; i++) {
        int c = tid + i * 256;
        yr[c] = __float2half((v[i] - mean) * rstd * g[c] + b[c]);
    }
}

// ---------------------------------------------------------------------------
// fp16 warp-MMA GEMM — occupancy-optimized: 512 threads (16 warps), warp
// tile 32x32 (acc 32 regs/thread), so 2 CTAs fit the RF at ~64 regs ->
// 32 warps/SM (2x the previous 16). Same CTA tile 128x128, BK=32, 3-stage
// cp.async, ldmatrix fragments, mma.m16n8k16, fp32 accumulate.
// SMEM [3][128][40] halves each for A and B (stride 40 -> conflict-free).
// EPI: bit0=bias, bit1=residual(float), bit2=gelu.  OT: __half or float.
// ---------------------------------------------------------------------------
#define HSMEM_BYTES 61440

template <int EPI, typename OT>
__global__ void __launch_bounds__(512, 2) hgemm(
    const __half* __restrict__ A, const __half* __restrict__ BT, OT* __restrict__ C,
    const float* __restrict__ bias, const float* __restrict__ res,
    int K, int lda, int ldb, int ldc,
    size_t batchA, size_t batchB, size_t batchC)
{
    extern __shared__ __half hsm[];
    __half* As = hsm;            // [3][128][40]
    __half* Bs = hsm + 15360;    // [3][128][40]

    A  += (size_t)blockIdx.z * batchA;
    BT += (size_t)blockIdx.z * batchB;
    C  += (size_t)blockIdx.z * batchC;

    const int tid = threadIdx.x;
    const int m0 = blockIdx.y * 128, n0 = blockIdx.x * 128;
    const int wid = tid >> 5, lane = tid & 31;
    const int wm = (wid >> 2) * 32;     // 0,32,64,96
    const int wn = (wid & 3) * 32;      // 0,32,64,96
    const int gq = lane >> 2, tg = lane & 3;

    const uint32_t sA = smem_u32(As);
    const uint32_t sB = smem_u32(Bs);

    // gmem->smem: 4 threads per 64B row (1 cp16 each)
    const int row = tid >> 2, seg = tid & 3;

    auto loadA = [&](int st, int k0) {
        const __half* src = A + (size_t)(m0 + row) * lda + k0 + seg * 8;
        uint32_t dst = sA + (uint32_t)st * 10240 + (uint32_t)row * 80 + (uint32_t)seg * 16;
        cp16(dst, src);
    };
    auto loadB = [&](int st, int k0) {
        const __half* src = BT + (size_t)(n0 + row) * ldb + k0 + seg * 8;
        uint32_t dst = sB + (uint32_t)st * 10240 + (uint32_t)row * 80 + (uint32_t)seg * 16;
        cp16(dst, src);
    };

    // ldmatrix per-lane byte offsets (within a stage)
    const int arow_l = (lane & 7) | (((lane >> 3) & 1) << 3);  // 0..15
    const int aseg   = lane >> 4;                              // 0/1 (k half)
    const uint32_t aoffB = (uint32_t)(wm + arow_l) * 80 + (uint32_t)aseg * 16;
    const int brow_l = (lane & 7) + ((lane >> 4) << 3);        // 0..15
    const int bseg   = (lane >> 3) & 1;                        // 0/1 (k half)
    const uint32_t boffB = (uint32_t)(wn + brow_l) * 80 + (uint32_t)bseg * 16;

    float acc[2][4][4];
#pragma unroll
    for (int mi = 0; mi < 2; mi++)
#pragma unroll
        for (int ni = 0; ni < 4; ni++)
#pragma unroll
            for (int q = 0; q < 4; q++) acc[mi][ni][q] = 0.f;

    const int KT = K >> 5;
    loadA(0, 0);  loadB(0, 0);
    asm volatile("cp.async.commit_group;");
    loadA(1, 32); loadB(1, 32);
    asm volatile("cp.async.commit_group;");

    for (int kt = 0; kt < KT; ++kt) {
        const int buf = kt % 3;
        asm volatile("cp.async.wait_group 1;");
        __syncthreads();
        if (kt + 2 < KT) {
            const int st = (kt + 2) % 3;
            loadA(st, (kt + 2) * 32);
            loadB(st, (kt + 2) * 32);
        }
        asm volatile("cp.async.commit_group;");

        const uint32_t aB = sA + (uint32_t)buf * 10240 + aoffB;
        const uint32_t bB = sB + (uint32_t)buf * 10240 + boffB;
#pragma unroll
        for (int kk = 0; kk < 32; kk += 16) {
            uint32_t a[2][4], b[4][2];
#pragma unroll
            for (int mi = 0; mi < 2; mi++)
                ldsm4(a[mi][0], a[mi][1], a[mi][2], a[mi][3],
                      aB + (uint32_t)mi * (16 * 80) + (uint32_t)kk * 2);
#pragma unroll
            for (int p = 0; p < 2; p++)
                ldsm4(b[2 * p][0], b[2 * p][1], b[2 * p + 1][0], b[2 * p + 1][1],
                      bB + (uint32_t)p * (16 * 80) + (uint32_t)kk * 2);
#pragma unroll
            for (int mi = 0; mi < 2; mi++)
#pragma unroll
                for (int ni = 0; ni < 4; ni++)
                    mma_f16(acc[mi][ni], a[mi], b[ni]);
        }
    }

    // epilogue
#pragma unroll
    for (int mi = 0; mi < 2; mi++) {
        const int r0 = m0 + wm + mi * 16 + gq;
#pragma unroll
        for (int ni = 0; ni < 4; ni++) {
            const int c = n0 + wn + ni * 8 + 2 * tg;
            float2 v01 = make_float2(acc[mi][ni][0], acc[mi][ni][1]);
            float2 v23 = make_float2(acc[mi][ni][2], acc[mi][ni][3]);
            if (EPI & 1) {
                float2 bv = *(const float2*)(bias + c);
                v01.x += bv.x; v01.y += bv.y;
                v23.x += bv.x; v23.y += bv.y;
            }
            if (EPI & 4) {
                v01.x = gelu_exact(v01.x); v01.y = gelu_exact(v01.y);
                v23.x = gelu_exact(v23.x); v23.y = gelu_exact(v23.y);
            }
            size_t off0 = (size_t)r0 * ldc + c;
            size_t off1 = (size_t)(r0 + 8) * ldc + c;
            if (EPI & 2) {
                float2 q0 = *(const float2*)(res + off0);
                float2 q1 = *(const float2*)(res + off1);
                v01.x += q0.x; v01.y += q0.y;
                v23.x += q1.x; v23.y += q1.y;
            }
            if constexpr (sizeof(OT) == 2) {
                *(__half2*)((__half*)C + off0) = __floats2half2_rn(v01.x, v01.y);
                *(__half2*)((__half*)C + off1) = __floats2half2_rn(v23.x, v23.y);
            } else {
                *(float2*)((float*)C + off0) = v01;
                *(float2*)((float*)C + off1) = v23;
            }
        }
    }
}

// ---------------------------------------------------------------------------
// Sequential MPS recurrence — R10 exact version (best measured).
// One WARP per (b,h) chain; 8-stage cp.async prefetch (distance 7); lane j
// owns row j (32 halves = 64B); h fp32 in double-buffered smem; fp32 accum;
// tanh.approx; one syncwarp per step.
// ---------------------------------------------------------------------------
__global__ void __launch_bounds__(32, 1) recurrence_kernel(
    const __half* __restrict__ Mg, __half* __restrict__ hs)
{
    __shared__ __align__(16) __half smh[8][32][40];
    __shared__ __align__(16) float hsm[2][32];
    const int j = threadIdx.x;
    const int b = blockIdx.x >> 4;
    const int h = blockIdx.x & 15;
    const __half* Mbh = Mg + ((size_t)h * BSROWS + (size_t)b * SEQ) * 1024;
    const uint32_t sbase = smem_u32(&smh[0][0][0]) + (uint32_t)j * 80;

    // preload tiles 0..6 into stages 0..6
#pragma unroll
    for (int t = 0; t < 7; t++) {
        const __half* src = Mbh + (size_t)t * 1024 + j * 32;
        const uint32_t dst = sbase + (uint32_t)t * 2560;
#pragma unroll
        for (int c = 0; c < 4; c++) cp16(dst + c * 16, src + c * 8);
        asm volatile("cp.async.commit_group;");
    }
    hsm[0][j] = 0.17677669529663688f;   // 1/sqrt(32)
    __syncwarp();

    __half* hsb = hs + ((size_t)b * SEQ) * 512 + h * 32 + j;

    for (int s = 0; s < SEQ; ++s) {
        if (s + 7 < SEQ) {
            const __half* src = Mbh + (size_t)(s + 7) * 1024 + j * 32;
            const uint32_t dst = sbase + (uint32_t)((s + 7) & 7) * 2560;
#pragma unroll
            for (int c = 0; c < 4; c++) cp16(dst + c * 16, src + c * 8);
        }
        asm volatile("cp.async.commit_group;");
        asm volatile("cp.async.wait_group 7;");

        const __half2* row2 = (const __half2*)&smh[s & 7][j][0];
        const float*   hv   = hsm[s & 1];
        float a0 = 0.f, a1 = 0.f, a2 = 0.f, a3 = 0.f;
#pragma unroll
        for (int c = 0; c < 8; c++) {
            float2 m0 = __half22float2(row2[2 * c]);
            float2 m1 = __half22float2(row2[2 * c + 1]);
            float4 hh = *(const float4*)&hv[c * 4];
            a0 = fmaf(hh.x, m0.x, a0);
            a1 = fmaf(hh.y, m0.y, a1);
            a2 = fmaf(hh.z, m1.x, a2);
            a3 = fmaf(hh.w, m1.y, a3);
        }
        float r = tanh_fast((a0 + a1) + (a2 + a3));
        hsm[(s + 1) & 1][j] = r;
        hsb[(size_t)s * 512] = __float2half(r);
        __syncwarp();
    }
}

// ---------------------------------------------------------------------------
// Launch
// ---------------------------------------------------------------------------
extern "C" void kernel_launch(void* const* d_in, const int* in_sizes, int n_in,
                              void* d_out, int out_size)
{
    const float* x     = (const float*)d_in[0];
    const float* ln1_g = (const float*)d_in[1];
    const float* ln1_b = (const float*)d_in[2];
    const float* W_in  = (const float*)d_in[3];
    const float* b_in  = (const float*)d_in[4];
    const float* A     = (const float*)d_in[5];
    const float* W_out = (const float*)d_in[6];
    const float* b_out = (const float*)d_in[7];
    const float* ln2_g = (const float*)d_in[8];
    const float* ln2_b = (const float*)d_in[9];
    const float* W1    = (const float*)d_in[10];
    const float* b1    = (const float*)d_in[11];
    const float* W2    = (const float*)d_in[12];
    const float* b2    = (const float*)d_in[13];
    float* out = (float*)d_out;

    float *x2;
    __half *lnh, *vh, *a2h, *Mh, *hsh, *ffnh, *winh, *wouth, *w1h, *w2h;
    cudaGetSymbolAddress((void**)&lnh,   g_lnh);
    cudaGetSymbolAddress((void**)&vh,    g_vh);
    cudaGetSymbolAddress((void**)&a2h,   g_a2h);
    cudaGetSymbolAddress((void**)&Mh,    g_Mh);
    cudaGetSymbolAddress((void**)&hsh,   g_hsh);
    cudaGetSymbolAddress((void**)&x2,    g_x2);
    cudaGetSymbolAddress((void**)&ffnh,  g_ffnh);
    cudaGetSymbolAddress((void**)&winh,  g_winh);
    cudaGetSymbolAddress((void**)&wouth, g_wouth);
    cudaGetSymbolAddress((void**)&w1h,   g_w1h);
    cudaGetSymbolAddress((void**)&w2h,   g_w2h);

    cudaFuncSetAttribute((const void*)(hgemm<0, __half>), cudaFuncAttributeMaxDynamicSharedMemorySize, HSMEM_BYTES);
    cudaFuncSetAttribute((const void*)(hgemm<1, __half>), cudaFuncAttributeMaxDynamicSharedMemorySize, HSMEM_BYTES);
    cudaFuncSetAttribute((const void*)(hgemm<5, __half>), cudaFuncAttributeMaxDynamicSharedMemorySize, HSMEM_BYTES);
    cudaFuncSetAttribute((const void*)(hgemm<3, float>),  cudaFuncAttributeMaxDynamicSharedMemorySize, HSMEM_BYTES);

    // 1) A rearrange -> fp16
    prep_A_kernel<<<4096, 256>>>(A, a2h);

    // 2) all weight transposes -> fp16 [N][K]
    tconv_all_kernel<<<9728, dim3(32, 8)>>>(W1, w1h, W2, w2h, W_in, winh, W_out, wouth);

    // 3) LN1 -> fp16
    ln_h_kernel<<<BSROWS, 256>>>(x, ln1_g, ln1_b, lnh);

    // 4) v = ln @ W_in + b_in   [8192 x 1024 x 1024]  fp16 out
    hgemm<1, __half><<<dim3(8, 64, 1), 512, HSMEM_BYTES>>>(
        lnh, winh, vh, b_in, nullptr, DIM, DIM, DIM, DIM, 0, 0, 0);

    // 5) M[h] = v[:, h*64:(h+1)*64] @ A2[h]^T   16 heads, [8192 x 1024 x 64]
    hgemm<0, __half><<<dim3(8, 64, NH), 512, HSMEM_BYTES>>>(
        vh, a2h, Mh, nullptr, nullptr, 64, DIM, 64, 1024,
        (size_t)64, (size_t)65536, (size_t)BSROWS * 1024);

    // 6) sequential recurrence -> hs (fp16)
    recurrence_kernel<<<64, 32>>>(Mh, hsh);

    // 7) x2 = x + hs @ W_out + b_out   [8192 x 1024 x 512]  fp32 out
    hgemm<3, float><<<dim3(8, 64, 1), 512, HSMEM_BYTES>>>(
        hsh, wouth, x2, b_out, x, 512, 512, 512, DIM, 0, 0, 0);

    // 8) LN2 -> fp16
    ln_h_kernel<<<BSROWS, 256>>>(x2, ln2_g, ln2_b, lnh);

    // 9) ffn = gelu(lnh @ W1 + b1)  [8192 x 4096 x 1024]  fp16 out
    hgemm<5, __half><<<dim3(32, 64, 1), 512, HSMEM_BYTES>>>(
        lnh, w1h, ffnh, b1, nullptr, DIM, DIM, DIM, DFF, 0, 0, 0);

    // 10) out = x2 + ffnh @ W2 + b2  [8192 x 1024 x 4096]  fp32 out
    hgemm<3, float><<<dim3(8, 64, 1), 512, HSMEM_BYTES>>>(
        ffnh, w2h, out, b2, x2, DFF, DFF, DFF, DIM, 0, 0, 0);
}